// round 2
// baseline (speedup 1.0000x reference)
#include <cuda_runtime.h>
#include <cuda_bf16.h>
#include <math.h>

// BboxSemanticAtt: grid[b,y,x] = sigmoid( sum_i c_i * [y1<=y<y2][x1<=x<x2] )
// preds: [B, 256, 5] f32 (conf, x1, y1, x2, y2 in [0,1)); out: [B, 512, 512] f32.
//
// One warp per output row: smem scatter of +/-c at x1/x2 (17-stride padded,
// conflict-free), register sequential scan + shfl warp scan, sigmoid, STG.128.

#define FEAT   512
#define NBOX   256
#define NWARPS 8
#define ROWS_PER_WARP 4
#define ROWS_PER_BLOCK (NWARPS * ROWS_PER_WARP)   // 32
#define ROW_PAD 544                               // 512 + 512/16 padding slots

__global__ __launch_bounds__(256, 8)
void bbox_att_kernel(const float* __restrict__ preds,
                     float* __restrict__ out,
                     int blocksPerBatch)
{
    __shared__ short sx1[NBOX], sx2[NBOX], sy1[NBOX], sy2[NBOX];
    __shared__ float sc[NBOX];
    __shared__ float rows[NWARPS][ROW_PAD];

    const int b       = blockIdx.x / blocksPerBatch;
    const int rowBase = (blockIdx.x % blocksPerBatch) * ROWS_PER_BLOCK;
    const int tid     = threadIdx.x;

    // ---- load + quantize boxes for this batch (once per block) ----
    if (tid < NBOX) {
        const float* p = preds + ((size_t)b * NBOX + tid) * 5;
        float c  = p[0];
        int x1 = (int)floorf(p[1] * 512.0f);
        int y1 = (int)floorf(p[2] * 512.0f);
        int x2 = (int)floorf(p[3] * 512.0f);
        int y2 = (int)floorf(p[4] * 512.0f);
        x1 = min(max(x1, 0), FEAT);  y1 = min(max(y1, 0), FEAT);
        x2 = min(max(x2, 0), FEAT);  y2 = min(max(y2, 0), FEAT);
        bool valid = (x2 > x1) && (y2 > y1);
        sx1[tid] = (short)x1;
        sx2[tid] = (short)x2;
        sy1[tid] = (short)(valid ? y1 : 0);   // invalid -> empty y-range
        sy2[tid] = (short)(valid ? y2 : 0);
        sc[tid]  = c;
    }
    __syncthreads();

    const int warp = tid >> 5;
    const int lane = tid & 31;
    float* row = rows[warp];

    #pragma unroll
    for (int r = 0; r < ROWS_PER_WARP; r++) {
        const int y = rowBase + warp * ROWS_PER_WARP + r;

        // zero the padded row (544 floats / 32 lanes = 17 each)
        #pragma unroll
        for (int i = lane; i < ROW_PAD; i += 32) row[i] = 0.0f;
        __syncwarp();

        // scatter +/-c for boxes active on this row (padded index p + p>>4)
        #pragma unroll
        for (int i = lane; i < NBOX; i += 32) {
            int yy1 = sy1[i], yy2 = sy2[i];
            if (y >= yy1 && y < yy2) {
                float c  = sc[i];
                int a1 = sx1[i];
                atomicAdd(&row[a1 + (a1 >> 4)],  c);
                int a2 = sx2[i];
                if (a2 < FEAT) atomicAdd(&row[a2 + (a2 >> 4)], -c);
            }
        }
        __syncwarp();

        // sequential inclusive scan of this lane's 16 contiguous elements.
        // element p lives at p + (p>>4); segment base = lane*16 -> addr lane*17,
        // contiguous for j<16, conflict-free across lanes (17 coprime 32).
        float v[16];
        const int base = lane * 17;
        float run = 0.0f;
        #pragma unroll
        for (int j = 0; j < 16; j++) { run += row[base + j]; v[j] = run; }

        // exclusive warp scan of segment totals
        float x = run;
        #pragma unroll
        for (int o = 1; o < 32; o <<= 1) {
            float t = __shfl_up_sync(0xFFFFFFFFu, x, o);
            if (lane >= o) x += t;
        }
        float pre = __shfl_up_sync(0xFFFFFFFFu, x, 1);
        if (lane == 0) pre = 0.0f;

        // sigmoid + vectorized store (lane writes 16 consecutive floats)
        float4 o4[4];
        float* ov = (float*)o4;
        #pragma unroll
        for (int j = 0; j < 16; j++) {
            float g = v[j] + pre;
            ov[j] = 1.0f / (1.0f + __expf(-g));
        }
        float4* dst = (float4*)(out + (((size_t)b * FEAT + y) * FEAT) + lane * 16);
        dst[0] = o4[0]; dst[1] = o4[1]; dst[2] = o4[2]; dst[3] = o4[3];
    }
}

extern "C" void kernel_launch(void* const* d_in, const int* in_sizes, int n_in,
                              void* d_out, int out_size)
{
    const float* preds = (const float*)d_in[0];
    float* out = (float*)d_out;

    int B = in_sizes[0] / (NBOX * 5);         // 64 for the bench shapes
    int blocksPerBatch = FEAT / ROWS_PER_BLOCK;  // 16
    dim3 grid(B * blocksPerBatch);               // 1024
    dim3 block(256);
    bbox_att_kernel<<<grid, block>>>(preds, out, blocksPerBatch);
}

// round 3
// speedup vs baseline: 1.0175x; 1.0175x over previous
#include <cuda_runtime.h>
#include <cuda_bf16.h>
#include <math.h>

// BboxSemanticAtt: grid[b,y,x] = sigmoid( sum_i c_i * [y1<=y<y2][x1<=x<x2] )
// preds: [B, 256, 5] f32 (conf, x1, y1, x2, y2 in [0,1)); out: [B, 512, 512] f32.
//
// One warp per output row: smem scatter of +/-c at x1/x2 (17-stride padded,
// conflict-free), register sequential scan + shfl warp scan, sigmoid, STG.128.

#define FEAT   512
#define NBOX   256
#define NWARPS 8
#define ROWS_PER_WARP 4
#define ROWS_PER_BLOCK (NWARPS * ROWS_PER_WARP)   // 32
#define ROW_PAD 544                               // 512 + 512/16 padding slots

__global__ __launch_bounds__(256, 8)
void bbox_att_kernel(const float* __restrict__ preds,
                     float* __restrict__ out,
                     int blocksPerBatch)
{
    __shared__ short sx1[NBOX], sx2[NBOX], sy1[NBOX], sy2[NBOX];
    __shared__ float sc[NBOX];
    __shared__ float rows[NWARPS][ROW_PAD];

    const int b       = blockIdx.x / blocksPerBatch;
    const int rowBase = (blockIdx.x % blocksPerBatch) * ROWS_PER_BLOCK;
    const int tid     = threadIdx.x;

    // ---- load + quantize boxes for this batch (once per block) ----
    if (tid < NBOX) {
        const float* p = preds + ((size_t)b * NBOX + tid) * 5;
        float c  = p[0];
        int x1 = (int)floorf(p[1] * 512.0f);
        int y1 = (int)floorf(p[2] * 512.0f);
        int x2 = (int)floorf(p[3] * 512.0f);
        int y2 = (int)floorf(p[4] * 512.0f);
        x1 = min(max(x1, 0), FEAT);  y1 = min(max(y1, 0), FEAT);
        x2 = min(max(x2, 0), FEAT);  y2 = min(max(y2, 0), FEAT);
        bool valid = (x2 > x1) && (y2 > y1);
        sx1[tid] = (short)x1;
        sx2[tid] = (short)x2;
        sy1[tid] = (short)(valid ? y1 : 0);   // invalid -> empty y-range
        sy2[tid] = (short)(valid ? y2 : 0);
        sc[tid]  = c;
    }
    __syncthreads();

    const int warp = tid >> 5;
    const int lane = tid & 31;
    float* row = rows[warp];

    #pragma unroll
    for (int r = 0; r < ROWS_PER_WARP; r++) {
        const int y = rowBase + warp * ROWS_PER_WARP + r;

        // zero the padded row (544 floats / 32 lanes = 17 each)
        #pragma unroll
        for (int i = lane; i < ROW_PAD; i += 32) row[i] = 0.0f;
        __syncwarp();

        // scatter +/-c for boxes active on this row (padded index p + p>>4)
        #pragma unroll
        for (int i = lane; i < NBOX; i += 32) {
            int yy1 = sy1[i], yy2 = sy2[i];
            if (y >= yy1 && y < yy2) {
                float c  = sc[i];
                int a1 = sx1[i];
                atomicAdd(&row[a1 + (a1 >> 4)],  c);
                int a2 = sx2[i];
                if (a2 < FEAT) atomicAdd(&row[a2 + (a2 >> 4)], -c);
            }
        }
        __syncwarp();

        // sequential inclusive scan of this lane's 16 contiguous elements.
        // element p lives at p + (p>>4); segment base = lane*16 -> addr lane*17,
        // contiguous for j<16, conflict-free across lanes (17 coprime 32).
        float v[16];
        const int base = lane * 17;
        float run = 0.0f;
        #pragma unroll
        for (int j = 0; j < 16; j++) { run += row[base + j]; v[j] = run; }

        // exclusive warp scan of segment totals
        float x = run;
        #pragma unroll
        for (int o = 1; o < 32; o <<= 1) {
            float t = __shfl_up_sync(0xFFFFFFFFu, x, o);
            if (lane >= o) x += t;
        }
        float pre = __shfl_up_sync(0xFFFFFFFFu, x, 1);
        if (lane == 0) pre = 0.0f;

        // sigmoid + vectorized store (lane writes 16 consecutive floats)
        float4 o4[4];
        float* ov = (float*)o4;
        #pragma unroll
        for (int j = 0; j < 16; j++) {
            float g = v[j] + pre;
            ov[j] = 1.0f / (1.0f + __expf(-g));
        }
        float4* dst = (float4*)(out + (((size_t)b * FEAT + y) * FEAT) + lane * 16);
        dst[0] = o4[0]; dst[1] = o4[1]; dst[2] = o4[2]; dst[3] = o4[3];
    }
}

extern "C" void kernel_launch(void* const* d_in, const int* in_sizes, int n_in,
                              void* d_out, int out_size)
{
    const float* preds = (const float*)d_in[0];
    float* out = (float*)d_out;

    int B = in_sizes[0] / (NBOX * 5);         // 64 for the bench shapes
    int blocksPerBatch = FEAT / ROWS_PER_BLOCK;  // 16
    dim3 grid(B * blocksPerBatch);               // 1024
    dim3 block(256);
    bbox_att_kernel<<<grid, block>>>(preds, out, blocksPerBatch);
}

// round 4
// speedup vs baseline: 1.4464x; 1.4215x over previous
#include <cuda_runtime.h>
#include <cuda_bf16.h>
#include <math.h>

// BboxSemanticAtt: out[b,y,x] = sigmoid( sum_i c_i * [y1<=y<y2][x1<=x<x2] )
// preds: [B, 256, 5] f32; out: [B, 512, 512] f32.
//
// Warp owns a 16-row chunk. Build first row via smem corner-scatter + scan,
// keep row VALUES in registers, then update incrementally: per row only the
// boxes entering (y1==y) / exiting (y2==y) apply a predicated range-add to
// the registers. Events pre-compacted per chunk; sigmoid via MUFU (EX2+RCP).

#define FEAT   512
#define NBOX   256
#define NWARPS 4
#define CHUNK  16
#define ROWS_PER_BLOCK (NWARPS * CHUNK)   // 64
#define ROW_PAD 544                        // 512 + 512/16 padding slots
#define MAXEV  512                         // worst case: 2 events per box

__global__ __launch_bounds__(128, 8)
void bbox_att_kernel(const float* __restrict__ preds,
                     float* __restrict__ out,
                     int blocksPerBatch)
{
    __shared__ int   sx12[NBOX];                 // x1 | (x2 << 16)
    __shared__ int   sy12[NBOX];                 // y1 | (y2 << 16), 0 if invalid
    __shared__ float sc  [NBOX];
    __shared__ float rows[NWARPS][ROW_PAD];      // first-row build scratch
    __shared__ unsigned evPack[NWARPS][MAXEV];   // x1 | x2<<10 | rowoff<<20
    __shared__ float    evC  [NWARPS][MAXEV];    // signed confidence
    __shared__ int      evCnt[NWARPS];

    const int b    = blockIdx.x / blocksPerBatch;
    const int tid  = threadIdx.x;
    const int warp = tid >> 5;
    const int lane = tid & 31;
    const int y0   = (blockIdx.x % blocksPerBatch) * ROWS_PER_BLOCK + warp * CHUNK;

    // ---- load + quantize boxes for this batch (once per block) ----
    for (int i = tid; i < NBOX; i += 128) {
        const float* p = preds + ((size_t)b * NBOX + i) * 5;
        float c  = p[0];
        int x1 = (int)floorf(p[1] * 512.0f);
        int y1 = (int)floorf(p[2] * 512.0f);
        int x2 = (int)floorf(p[3] * 512.0f);
        int y2 = (int)floorf(p[4] * 512.0f);
        x1 = min(max(x1, 0), FEAT);  y1 = min(max(y1, 0), FEAT);
        x2 = min(max(x2, 0), FEAT);  y2 = min(max(y2, 0), FEAT);
        bool valid = (x2 > x1) && (y2 > y1);
        sx12[i] = x1 | (x2 << 16);
        sy12[i] = valid ? (y1 | (y2 << 16)) : 0;   // invalid -> empty range
        sc[i]   = c;
    }
    if (tid < NWARPS) evCnt[tid] = 0;
    __syncthreads();

    float* row = rows[warp];

    // ---- zero the build row ----
    #pragma unroll
    for (int i = lane; i < ROW_PAD; i += 32) row[i] = 0.0f;
    __syncwarp();

    // ---- one pass over boxes: scatter boxes active at y0, collect events ----
    #pragma unroll
    for (int i = lane; i < NBOX; i += 32) {
        int y12 = sy12[i];
        int y1 = y12 & 0xFFFF, y2 = (y12 >> 16) & 0xFFFF;
        int x12 = sx12[i];
        float c = sc[i];
        if (y1 <= y0 && y0 < y2) {                    // active on first row
            int a1 = x12 & 0xFFFF;
            atomicAdd(&row[a1 + (a1 >> 4)],  c);
            int a2 = (x12 >> 16) & 0xFFFF;
            if (a2 < FEAT) atomicAdd(&row[a2 + (a2 >> 4)], -c);
        }
        unsigned xp = (unsigned)(x12 & 0xFFFF) | ((unsigned)((x12 >> 16) & 0xFFFF) << 10);
        if (y1 > y0 && y1 < y0 + CHUNK) {             // box enters inside chunk
            int e = atomicAdd(&evCnt[warp], 1);
            evPack[warp][e] = xp | ((unsigned)(y1 - y0) << 20);
            evC[warp][e]    = c;
        }
        if (y2 > y0 && y2 < y0 + CHUNK) {             // box exits inside chunk
            int e = atomicAdd(&evCnt[warp], 1);
            evPack[warp][e] = xp | ((unsigned)(y2 - y0) << 20);
            evC[warp][e]    = -c;
        }
    }
    __syncwarp();
    const int nev = evCnt[warp];

    // ---- scan first row into registers (conflict-free: stride 17) ----
    float v[16];
    {
        const int base = lane * 17;
        float run = 0.0f;
        #pragma unroll
        for (int j = 0; j < 16; j++) { run += row[base + j]; v[j] = run; }

        float x = run;
        #pragma unroll
        for (int o = 1; o < 32; o <<= 1) {
            float t = __shfl_up_sync(0xFFFFFFFFu, x, o);
            if (lane >= o) x += t;
        }
        float pre = __shfl_up_sync(0xFFFFFFFFu, x, 1);
        if (lane == 0) pre = 0.0f;
        #pragma unroll
        for (int j = 0; j < 16; j++) v[j] += pre;
    }

    // ---- per-row: sigmoid + store, then apply next row's events ----
    const int s = lane * 16;
    float* dstBase = out + (((size_t)b * FEAT + y0) * FEAT) + s;

    for (int r = 0; r < CHUNK; r++) {
        float4 o4[4];
        float* ov = (float*)o4;
        #pragma unroll
        for (int j = 0; j < 16; j++) {
            ov[j] = __fdividef(1.0f, 1.0f + __expf(-v[j]));
        }
        float4* dst = (float4*)(dstBase + (size_t)r * FEAT);
        dst[0] = o4[0]; dst[1] = o4[1]; dst[2] = o4[2]; dst[3] = o4[3];

        if (r + 1 < CHUNK) {
            const int rn = r + 1;
            const int iters = (nev + 31) >> 5;
            for (int it = 0; it < iters; it++) {
                int t = it * 32 + lane;
                unsigned pk = 0; float cc = 0.0f; bool m = false;
                if (t < nev) {
                    pk = evPack[warp][t];
                    cc = evC[warp][t];
                    m  = ((int)(pk >> 20) == rn);
                }
                unsigned bal = __ballot_sync(0xFFFFFFFFu, m);
                while (bal) {
                    int src = __ffs(bal) - 1; bal &= bal - 1;
                    unsigned p2 = __shfl_sync(0xFFFFFFFFu, pk, src);
                    float    c2 = __shfl_sync(0xFFFFFFFFu, cc, src);
                    int x1 = (int)(p2 & 0x3FF);
                    int x2 = (int)((p2 >> 10) & 0x3FF);
                    int lo = max(x1 - s, 0);
                    int hi = min(x2 - s, 16);
                    if (lo < hi) {
                        #pragma unroll
                        for (int j = 0; j < 16; j++)
                            if (j >= lo && j < hi) v[j] += c2;
                    }
                }
            }
        }
    }
}

extern "C" void kernel_launch(void* const* d_in, const int* in_sizes, int n_in,
                              void* d_out, int out_size)
{
    const float* preds = (const float*)d_in[0];
    float* out = (float*)d_out;

    int B = in_sizes[0] / (NBOX * 5);               // 64 for bench shapes
    int blocksPerBatch = FEAT / ROWS_PER_BLOCK;     // 8
    dim3 grid(B * blocksPerBatch);                  // 512
    dim3 block(128);
    bbox_att_kernel<<<grid, block>>>(preds, out, blocksPerBatch);
}

// round 5
// speedup vs baseline: 1.5818x; 1.0936x over previous
#include <cuda_runtime.h>
#include <cuda_bf16.h>
#include <math.h>

// BboxSemanticAtt: out[b,y,x] = sigmoid( sum_i c_i * [y1<=y<y2][x1<=x<x2] )
// preds: [B, 256, 5] f32; out: [B, 512, 512] f32.
//
// Warp owns an 8-row chunk. Build first row via smem corner-scatter + scan,
// keep row VALUES in registers, update incrementally per row with the boxes
// entering/exiting at that row (block-level pre-compacted event list).
// Sigmoid via single MUFU.TANH: sigma(g) = 0.5*tanh(g/2)+0.5.

#define FEAT   512
#define NBOX   256
#define NWARPS 4
#define CHUNK  8
#define ROWS_PER_BLOCK (NWARPS * CHUNK)   // 32
#define ROW_PAD 544                        // 512 + 512/16 padding slots
#define MAXEV  512                         // hard bound: 2 events per box

__global__ __launch_bounds__(128, 8)
void bbox_att_kernel(const float* __restrict__ preds,
                     float* __restrict__ out,
                     int blocksPerBatch)
{
    __shared__ int   sx12[NBOX];                 // x1 | (x2 << 16)
    __shared__ int   sy12[NBOX];                 // y1 | (y2 << 16), 0|0 if invalid
    __shared__ float sc  [NBOX];
    __shared__ float rows[NWARPS][ROW_PAD];      // first-row build scratch
    __shared__ unsigned evPack[MAXEV];           // x1 | x2<<10 | blockRowOff<<20
    __shared__ float    evC  [MAXEV];            // signed confidence
    __shared__ int      evCnt;

    const int b       = blockIdx.x / blocksPerBatch;
    const int rowBase = (blockIdx.x % blocksPerBatch) * ROWS_PER_BLOCK;
    const int tid     = threadIdx.x;
    const int warp    = tid >> 5;
    const int lane    = tid & 31;

    if (tid == 0) evCnt = 0;
    __syncthreads();

    // ---- load + quantize boxes; collect in-block enter/exit events ----
    for (int i = tid; i < NBOX; i += 128) {
        const float* p = preds + ((size_t)b * NBOX + i) * 5;
        float c  = p[0];
        int x1 = min(max((int)floorf(p[1] * 512.0f), 0), FEAT);
        int y1 = min(max((int)floorf(p[2] * 512.0f), 0), FEAT);
        int x2 = min(max((int)floorf(p[3] * 512.0f), 0), FEAT);
        int y2 = min(max((int)floorf(p[4] * 512.0f), 0), FEAT);
        bool valid = (x2 > x1) && (y2 > y1);
        if (!valid) { y1 = 0; y2 = 0; }             // empty y-range
        sx12[i] = x1 | (x2 << 16);
        sy12[i] = y1 | (y2 << 16);
        sc[i]   = c;

        unsigned xp = (unsigned)x1 | ((unsigned)x2 << 10);
        int d1 = y1 - rowBase;                       // enter event
        if (d1 > 0 && d1 < ROWS_PER_BLOCK && (d1 & (CHUNK - 1))) {
            int e = atomicAdd(&evCnt, 1);
            evPack[e] = xp | ((unsigned)d1 << 20);
            evC[e]    = c;
        }
        int d2 = y2 - rowBase;                       // exit event
        if (d2 > 0 && d2 < ROWS_PER_BLOCK && (d2 & (CHUNK - 1))) {
            int e = atomicAdd(&evCnt, 1);
            evPack[e] = xp | ((unsigned)d2 << 20);
            evC[e]    = -c;
        }
    }
    __syncthreads();
    const int nev = evCnt;

    const int y0 = rowBase + warp * CHUNK;
    float* row = rows[warp];

    // ---- zero the build row ----
    #pragma unroll
    for (int i = lane; i < ROW_PAD; i += 32) row[i] = 0.0f;
    __syncwarp();

    // ---- scatter boxes active at y0 (padded index p + p>>4) ----
    #pragma unroll
    for (int i = lane; i < NBOX; i += 32) {
        int y12 = sy12[i];
        int y1 = y12 & 0xFFFF, y2 = y12 >> 16;
        if (y1 <= y0 && y0 < y2) {
            int x12 = sx12[i];
            float c = sc[i];
            int a1 = x12 & 0xFFFF;
            atomicAdd(&row[a1 + (a1 >> 4)],  c);
            int a2 = x12 >> 16;
            if (a2 < FEAT) atomicAdd(&row[a2 + (a2 >> 4)], -c);
        }
    }
    __syncwarp();

    // ---- scan first row into registers (conflict-free: stride 17) ----
    float v[16];
    {
        const int base = lane * 17;
        float run = 0.0f;
        #pragma unroll
        for (int j = 0; j < 16; j++) { run += row[base + j]; v[j] = run; }

        float x = run;
        #pragma unroll
        for (int o = 1; o < 32; o <<= 1) {
            float t = __shfl_up_sync(0xFFFFFFFFu, x, o);
            if (lane >= o) x += t;
        }
        float pre = __shfl_up_sync(0xFFFFFFFFu, x, 1);
        if (lane == 0) pre = 0.0f;
        #pragma unroll
        for (int j = 0; j < 16; j++) v[j] += pre;
    }

    // ---- per-row: sigmoid + store, then apply next row's events ----
    const int s = lane * 16;
    float* dstBase = out + (((size_t)b * FEAT + y0) * FEAT) + s;
    const int iters = (nev + 31) >> 5;

    for (int r = 0; r < CHUNK; r++) {
        float4 o4[4];
        float* ov = (float*)o4;
        #pragma unroll
        for (int j = 0; j < 16; j++) {
            float t;
            asm("tanh.approx.f32 %0, %1;" : "=f"(t) : "f"(0.5f * v[j]));
            ov[j] = fmaf(0.5f, t, 0.5f);
        }
        float4* dst = (float4*)(dstBase + (size_t)r * FEAT);
        dst[0] = o4[0]; dst[1] = o4[1]; dst[2] = o4[2]; dst[3] = o4[3];

        if (r + 1 < CHUNK) {
            const int target = (y0 - rowBase) + r + 1;
            for (int it = 0; it < iters; it++) {
                int t = it * 32 + lane;
                unsigned pk = 0; float cc = 0.0f; bool m = false;
                if (t < nev) {
                    pk = evPack[t];
                    cc = evC[t];
                    m  = ((int)(pk >> 20) == target);
                }
                unsigned bal = __ballot_sync(0xFFFFFFFFu, m);
                while (bal) {
                    int src = __ffs(bal) - 1; bal &= bal - 1;
                    unsigned p2 = __shfl_sync(0xFFFFFFFFu, pk, src);
                    float    c2 = __shfl_sync(0xFFFFFFFFu, cc, src);
                    int lo = max((int)(p2 & 0x3FF) - s, 0);
                    int hi = min((int)((p2 >> 10) & 0x3FF) - s, 16);
                    if (lo < hi) {
                        #pragma unroll
                        for (int j = 0; j < 16; j++)
                            if (j >= lo && j < hi) v[j] += c2;
                    }
                }
            }
        }
    }
}

extern "C" void kernel_launch(void* const* d_in, const int* in_sizes, int n_in,
                              void* d_out, int out_size)
{
    const float* preds = (const float*)d_in[0];
    float* out = (float*)d_out;

    int B = in_sizes[0] / (NBOX * 5);               // 64 for bench shapes
    int blocksPerBatch = FEAT / ROWS_PER_BLOCK;     // 16
    dim3 grid(B * blocksPerBatch);                  // 1024
    dim3 block(128);
    bbox_att_kernel<<<grid, block>>>(preds, out, blocksPerBatch);
}